// round 13
// baseline (speedup 1.0000x reference)
#include <cuda_runtime.h>
#include <cstdint>

// ---------------------------------------------------------------------------
// Problem constants
// ---------------------------------------------------------------------------
#define BB     128          // batch
#define DD     256          // embedding dim
#define NSAMP  1000         // MC samples
#define KK     8            // top-k
#define NSHAPES 8000
#define HALF_ELEMS 8192000u // (128*1000*128)/2 -> element pairing offset
#define MAXC   32           // candidate cap per row (overflow -> inline fallback)
#define CH     4            // chunks per sampling unit (fat tickets)
#define SCH    250          // samples per chunk (CH*SCH == NSAMP)
#define NBLK   888          // persistent grid (148 SM x 6 blocks)

// ---------------------------------------------------------------------------
// Device scratch (no allocations; zero-initialized at load, self-reset at the
// end of every cand run for graph replays)
// ---------------------------------------------------------------------------
__device__ float  g_pred[BB * BB];
__device__ float  g_tgt [BB * BB];
__device__ int    g_cnt1[BB * KK * BB];
__device__ int    g_cnt2[BB * KK * BB];
__device__ float  g_cval[2 * BB * MAXC];
__device__ int    g_cidx[2 * BB * MAXC];
__device__ int    g_cm  [2 * BB];
__device__ int    g_wl  [2 * BB];         // worklist: units (pass*128+row), m>8
__device__ int    g_nwork;
__device__ int    g_rowexp[BB];           // expected sampled chunks per row
__device__ unsigned int g_ticket;
__device__ unsigned int g_rowdone[BB];
__device__ unsigned long long g_sum;      // 2^20 fixed-point loss accumulator
__device__ unsigned int g_done;           // rows reduced
__device__ unsigned int g_exit;           // cand blocks exited (reset protocol)

// ---------------------------------------------------------------------------
// threefry2x32 — exactly JAX's schedule
// ---------------------------------------------------------------------------
__host__ __device__ __forceinline__ void threefry2x32(
    uint32_t k0, uint32_t k1, uint32_t x0, uint32_t x1,
    uint32_t& o0, uint32_t& o1)
{
    uint32_t ks2 = k0 ^ k1 ^ 0x1BD11BDAu;
#define TF_ROUND(r) { x0 += x1; x1 = (x1 << (r)) | (x1 >> (32 - (r))); x1 ^= x0; }
    x0 += k0; x1 += k1;
    TF_ROUND(13) TF_ROUND(15) TF_ROUND(26) TF_ROUND(6)
    x0 += k1;  x1 += ks2 + 1u;
    TF_ROUND(17) TF_ROUND(29) TF_ROUND(16) TF_ROUND(24)
    x0 += ks2; x1 += k0 + 2u;
    TF_ROUND(13) TF_ROUND(15) TF_ROUND(26) TF_ROUND(6)
    x0 += k0;  x1 += k1 + 3u;
    TF_ROUND(17) TF_ROUND(29) TF_ROUND(16) TF_ROUND(24)
    x0 += k1;  x1 += ks2 + 4u;
    TF_ROUND(13) TF_ROUND(15) TF_ROUND(26) TF_ROUND(6)
    x0 += ks2; x1 += k0 + 5u;
#undef TF_ROUND
    o0 = x0; o1 = x1;
}

// ---------------------------------------------------------------------------
// bits -> N(0,1): JAX uniform bit-trick + XLA ErfInv32 polynomial (fast log).
// ---------------------------------------------------------------------------
__device__ __forceinline__ float jx_normal(uint32_t bits)
{
    float f = __uint_as_float((bits >> 9) | 0x3f800000u) - 1.0f;   // [0,1)
    const float lo = -0.99999994f;                                  // nextafter(-1,0)
    float u = __fadd_rn(__fmul_rn(f, 2.0f), lo);
    u = fmaxf(u, lo);

    float w = -__logf(fmaf(-u, u, 1.0f));     // ~= -log1p(-u*u)
    float p;
    if (w < 5.0f) {
        w -= 2.5f;
        p = 2.81022636e-08f;
        p = fmaf(p, w,  3.43273939e-07f);
        p = fmaf(p, w, -3.5233877e-06f);
        p = fmaf(p, w, -4.39150654e-06f);
        p = fmaf(p, w,  0.00021858087f);
        p = fmaf(p, w, -0.00125372503f);
        p = fmaf(p, w, -0.00417768164f);
        p = fmaf(p, w,  0.246640727f);
        p = fmaf(p, w,  1.50140941f);
    } else {
        w = sqrtf(w) - 3.0f;
        p = -0.000200214257f;
        p = fmaf(p, w,  0.000100950558f);
        p = fmaf(p, w,  0.00134934322f);
        p = fmaf(p, w, -0.00367342844f);
        p = fmaf(p, w,  0.00573950773f);
        p = fmaf(p, w, -0.0076224613f);
        p = fmaf(p, w,  0.00943887047f);
        p = fmaf(p, w,  1.00167406f);
        p = fmaf(p, w,  2.83297682f);
    }
    return __fmul_rn(1.41421354f, __fmul_rn(p, u));   // sqrt(2)*erfinv(u)
}

// order-isomorphic float map + invidx packing (25-bit value, 7-bit 127-idx)
__device__ __forceinline__ uint32_t pack_key(float v, uint32_t invidx)
{
    uint32_t b = __float_as_uint(v);
    uint32_t k = b ^ ((uint32_t)((int32_t)b >> 31) | 0x80000000u);
    return (k & 0xFFFFFF80u) | invidx;
}

__device__ __forceinline__ uint32_t perturb_pack(float x, uint32_t bits, float sigma,
                                                 uint32_t invidx)
{
    float v = __fadd_rn(x, __fmul_rn(sigma, jx_normal(bits)));
    return pack_key(v, invidx);
}

// decode truncated packed key -> float <= original value
__device__ __forceinline__ float decode_key_low(uint32_t k)
{
    uint32_t kv = k & 0xFFFFFF80u;
    uint32_t b  = (kv & 0x80000000u) ? (kv & 0x7FFFFFFFu) : ~kv;
    return __uint_as_float(b);
}

// ---------------------------------------------------------------------------
// Full-128 helpers
// ---------------------------------------------------------------------------
#define SWAPD(a,b) { uint32_t t_ = (a) < (b) ? (b) : (a); (b) = (a) < (b) ? (a) : (b); (a) = t_; }

__device__ __forceinline__ uint32_t eighth_key(uint32_t a0, uint32_t a1,
                                               uint32_t a2, uint32_t a3)
{
    SWAPD(a0,a1) SWAPD(a2,a3) SWAPD(a0,a2) SWAPD(a1,a3) SWAPD(a1,a2)
    uint32_t mx = 0;
    int pos = 0;
#pragma unroll
    for (int r = 0; r < 8; ++r) {
        mx = __reduce_max_sync(0xffffffffu, a0);
        if (a0 == mx) {
            ++pos;
            a0 = (pos == 1) ? a1 : (pos == 2) ? a2 : (pos == 3) ? a3 : 0u;
        }
    }
    return mx;
}

__device__ __forceinline__ void topk8_single_accum(
    uint32_t a0, uint32_t a1, uint32_t a2, uint32_t a3,
    int lane, int* __restrict__ scnt)
{
    SWAPD(a0,a1) SWAPD(a2,a3) SWAPD(a0,a2) SWAPD(a1,a3) SWAPD(a1,a2)
    uint32_t wonq = 0;
#pragma unroll
    for (int r = 0; r < 8; ++r) {
        uint32_t mx = __reduce_max_sync(0xffffffffu, a0);
        if (a0 == mx) {
            wonq |= 1u << (3u - ((a0 & 127u) >> 5));
            a0 = a1; a1 = a2; a2 = a3; a3 = 0u;
        }
    }
    uint32_t W0 = __ballot_sync(0xffffffffu,  wonq & 1u);
    uint32_t W1 = __ballot_sync(0xffffffffu, (wonq >> 1) & 1u);
    uint32_t W2 = __ballot_sync(0xffffffffu, (wonq >> 2) & 1u);
    uint32_t W3 = __ballot_sync(0xffffffffu, (wonq >> 3) & 1u);

    int r = lane & 7;
    int c0 = __popc(W0);
    int c01 = c0 + __popc(W1);
    int c012 = c01 + __popc(W2);
    uint32_t word = W0; int base = 0, n = r;
    if (r >= c0)   { word = W1; base = 32; n = r - c0; }
    if (r >= c01)  { word = W2; base = 64; n = r - c01; }
    if (r >= c012) { word = W3; base = 96; n = r - c012; }

    unsigned pos = 0, c;
    c = __popc(word & 0xFFFFu); if ((unsigned)n >= c) { n -= c; pos += 16; word >>= 16; }
    c = __popc(word & 0xFFu);   if ((unsigned)n >= c) { n -= c; pos += 8;  word >>= 8; }
    c = __popc(word & 0xFu);    if ((unsigned)n >= c) { n -= c; pos += 4;  word >>= 4; }
    c = __popc(word & 0x3u);    if ((unsigned)n >= c) { n -= c; pos += 2;  word >>= 2; }
    c = word & 1u;              if ((unsigned)n >= c) { pos += 1; }

    if (lane < 8)
        atomicAdd(&scnt[r * BB + base + (int)pos], 1);
}

// ---------------------------------------------------------------------------
// Kernel 1: pred_sim GEMM (split-K) + tgt gather + zeroing + candidates
// + worklist + m==8 deterministic counts + fully-deterministic-row reduction.
// grid(128) block(256). Relies on run-state zeroed by previous cand run.
// ---------------------------------------------------------------------------
__global__ void __launch_bounds__(256) prep_kernel(
    const float* __restrict__ cad, const float* __restrict__ scan,
    const float* __restrict__ sim, const int* __restrict__ scannet_idx,
    const int* __restrict__ shapenet_idx,
    float margin1, float margin2, float* __restrict__ out)
{
    __shared__ float row[DD];
    __shared__ float s_pred[BB], s_tg[BB];
    __shared__ float s_part[256];
    __shared__ int   s_m[2];
    __shared__ int   s_rd[2][8];
    int i = blockIdx.x, tid = threadIdx.x;
    int j = tid & 127, h = tid >> 7;

    if (tid < 128) {
        row[tid]       = scan[i * DD + tid];
        row[tid + 128] = scan[i * DD + 128 + tid];
    }
    {   // zero row i of both counter arrays
        int t = i * 256 + tid;
        int4 z = make_int4(0, 0, 0, 0);
        reinterpret_cast<int4*>(g_cnt1)[t] = z;
        reinterpret_cast<int4*>(g_cnt2)[t] = z;
    }
    __syncthreads();

    const float4* c4 = reinterpret_cast<const float4*>(cad + (size_t)j * DD) + h * 32;
    float a0 = 0.f, a1 = 0.f, a2 = 0.f, a3 = 0.f;
#pragma unroll
    for (int t = 0; t < 32; ++t) {
        float4 v = c4[t];
        int base = h * 128 + t * 4;
        a0 = fmaf(row[base + 0], v.x, a0);
        a1 = fmaf(row[base + 1], v.y, a1);
        a2 = fmaf(row[base + 2], v.z, a2);
        a3 = fmaf(row[base + 3], v.w, a3);
    }
    s_part[tid] = (a0 + a1) + (a2 + a3);
    __syncthreads();

    if (tid < 128) {
        float acc = s_part[tid] + s_part[tid + 128];
        float tv  = sim[(size_t)scannet_idx[i] * NSHAPES + shapenet_idx[tid]];
        g_pred[i * BB + tid] = acc;  s_pred[tid] = acc;
        g_tgt [i * BB + tid] = tv;   s_tg[tid]   = tv;
    }
    __syncthreads();

    int w = tid >> 5, lane = tid & 31;
    if (w < 2) {
        const float* v = w ? s_tg : s_pred;
        float margin = w ? margin2 : margin1;
        int* __restrict__ cnt = w ? g_cnt2 : g_cnt1;
        float v0 = v[lane], v1 = v[lane + 32], v2 = v[lane + 64], v3 = v[lane + 96];

        uint32_t k8 = eighth_key(pack_key(v0, 127u - lane),
                                 pack_key(v1, 95u  - lane),
                                 pack_key(v2, 63u  - lane),
                                 pack_key(v3, 31u  - lane));
        float thresh = decode_key_low(k8) - margin;

        int cbase = (w * BB + i) * MAXC;
        int mycand[4]; int mycnt = 0;
        int cnt_total = 0;
#pragma unroll
        for (int q = 0; q < 4; ++q) {
            float vq = (q == 0) ? v0 : (q == 1) ? v1 : (q == 2) ? v2 : v3;
            bool c = (vq >= thresh);
            uint32_t mask = __ballot_sync(0xffffffffu, c);
            if (c) {
                int pos = cnt_total + __popc(mask & ((1u << lane) - 1u));
                if (pos < MAXC) {
                    g_cval[cbase + pos] = vq;
                    g_cidx[cbase + pos] = q * 32 + lane;
                }
                if (pos < 8) s_rd[w][pos] = q * 32 + lane;
                if (mycnt < 4) mycand[mycnt] = (pos << 16) | (q * 32 + lane);
                ++mycnt;
            }
            cnt_total += __popc(mask);
        }
        if (lane == 0) {
            g_cm[w * BB + i] = cnt_total;
            s_m[w] = cnt_total;
            if (cnt_total > 8) {
                int p = atomicAdd(&g_nwork, 1);
                g_wl[p] = w * BB + i;
            }
        }

        if (cnt_total == 8) {   // deterministic counts
#pragma unroll
            for (int t = 0; t < 4; ++t) {
                if (t < mycnt) {
                    int pos = mycand[t] >> 16;
                    int d   = mycand[t] & 0xFFFF;
                    cnt[i * (KK * BB) + pos * BB + d] = NSAMP;
                }
            }
        }
    }
    __syncthreads();

    if (tid == 0) {
        int expv = ((s_m[0] > 8) ? CH : 0) + ((s_m[1] > 8) ? CH : 0);
        g_rowexp[i] = expv;
        if (expv == 0) {   // fully deterministic row: reduce right here
            float part = 0.0f;
#pragma unroll
            for (int r = 0; r < 8; ++r)
                if (s_rd[0][r] == s_rd[1][r]) part += s_tg[s_rd[0][r]];
            part *= (float)NSAMP * (float)NSAMP;
            long long fx = llrintf(part * 1048576.0f);
            atomicAdd(&g_sum, (unsigned long long)fx);
            __threadfence();
            if (atomicAdd(&g_done, 1u) == (unsigned)(BB - 1)) {
                unsigned long long s = atomicAdd(&g_sum, 0ull);
                out[0] = (float)(-((double)(long long)s / 1048576.0)
                                 / (1000.0 * 1000.0 * (double)(KK * BB)));
            }
        }
    }
}

// ---------------------------------------------------------------------------
// Kernel 2: persistent ticket sampler + fused reduction + replay reset.
// grid(NBLK) block(256). Tickets: t -> (unit = g_wl[t/CH], chunk = t%CH).
// ---------------------------------------------------------------------------
__global__ void __launch_bounds__(256, 6) cand_topk_kernel(
    uint32_t k0a, uint32_t k1a, uint32_t k0b, uint32_t k1b,
    float sig1, float sig2, float* __restrict__ out)
{
    __shared__ int   sCnt[KK * BB];
    __shared__ unsigned int s_t;
    __shared__ int   s_last;
    __shared__ float sw[8];

    int tid = threadIdx.x, lane = tid & 31, warp = tid >> 5;
    unsigned int total = (unsigned int)(g_nwork * CH);

    for (;;) {
        __syncthreads();                        // protect shared reuse
        if (tid == 0) s_t = atomicAdd(&g_ticket, 1u);
        __syncthreads();
        unsigned int t = s_t;
        if (t >= total) break;

        int unit  = g_wl[t / CH];
        int chunk = (int)(t % CH);
        int pass  = unit >> 7;
        int rowb  = unit & 127;

        int*     __restrict__ cnt = pass ? g_cnt2 : g_cnt1;
        uint32_t k0 = pass ? k0b : k0a;
        uint32_t k1 = pass ? k1b : k1a;
        float sigma = pass ? sig2 : sig1;

        int m = g_cm[unit];
        uint32_t rowbase = (uint32_t)rowb * (uint32_t)(NSAMP * BB);
        bool lohalf = rowb < 64;
        int nBegin = chunk * SCH;
        int nEnd   = nBegin + SCH;
        int cbase  = unit * MAXC;

        if (m <= MAXC) {
            if (tid < KK * MAXC) sCnt[tid] = 0;

            int nseg = 32 / m;
            int seg  = lane / m;
            int slot = lane - seg * m;
            bool active = seg < nseg;
            uint32_t segmask = ((m == 32) ? 0xffffffffu : ((1u << m) - 1u)) << (seg * m);

            float    x   = active ? g_cval[cbase + slot] : 0.0f;
            int      d   = active ? g_cidx[cbase + slot] : 0;
            uint32_t inv = 127u - (uint32_t)d;
            __syncthreads();

            int roundsMin = m - 8;
            bool useMin = (roundsMin <= 8);
            uint32_t ebase = rowbase + (uint32_t)d;

            for (int n0 = nBegin + warp * nseg; n0 < nEnd; n0 += 8 * nseg) {
                int nn = n0 + seg;
                bool valid = active && (nn < nEnd);

                uint32_t e   = ebase + (uint32_t)nn * (uint32_t)BB;
                uint32_t tx0 = lohalf ? e : e - HALF_ELEMS;
                uint32_t tx1 = lohalf ? e + HALF_ELEMS : e;
                uint32_t o0, o1;
                threefry2x32(k0, k1, tx0, tx1, o0, o1);
                uint32_t rb = lohalf ? o0 : o1;

                bool won = false;
                if (valid) {
                    uint32_t key = perturb_pack(x, rb, sigma, inv);
                    if (useMin) {
                        bool elim = false;
                        for (int r = 0; r < roundsMin; ++r) {
                            uint32_t mn = __reduce_min_sync(segmask, key);
                            bool er = (key == mn);
                            elim |= er;
                            if (er) key = 0xFFFFFFFFu;
                        }
                        won = !elim;
                    } else {
                        for (int r = 0; r < 8; ++r) {
                            uint32_t mx = __reduce_max_sync(segmask, key);
                            bool wr = (key == mx);
                            won |= wr;
                            if (wr) key = 0u;
                        }
                    }
                }
                uint32_t bal = __ballot_sync(0xffffffffu, won);
                if (won) {
                    int rank = __popc(bal & segmask & ((1u << lane) - 1u));
                    atomicAdd(&sCnt[rank * MAXC + slot], 1);
                }
            }
            __syncthreads();

            for (int tt = tid; tt < KK * m; tt += 256) {
                int rank = tt / m, sl = tt - rank * m;
                int v = sCnt[rank * MAXC + sl];
                if (v) atomicAdd(&cnt[rowb * (KK * BB) + rank * BB + g_cidx[cbase + sl]], v);
            }
        } else {
            // full-128 fallback (m > MAXC; astronomically rare)
            for (int tt = tid; tt < KK * BB; tt += 256) sCnt[tt] = 0;
            __syncthreads();

            const float* __restrict__ src = pass ? g_tgt : g_pred;
            float x0 = src[rowb * BB + lane];
            float x1 = src[rowb * BB + lane + 32];
            float x2 = src[rowb * BB + lane + 64];
            float x3 = src[rowb * BB + lane + 96];
            for (int n = nBegin + warp; n < nEnd; n += 8) {
                uint32_t a[4];
#pragma unroll
                for (int q = 0; q < 4; ++q) {
                    uint32_t e   = rowbase + (uint32_t)n * (uint32_t)BB + (uint32_t)(lane + 32 * q);
                    uint32_t tx0 = lohalf ? e : e - HALF_ELEMS;
                    uint32_t tx1 = lohalf ? e + HALF_ELEMS : e;
                    uint32_t o0, o1;
                    threefry2x32(k0, k1, tx0, tx1, o0, o1);
                    uint32_t rb = lohalf ? o0 : o1;
                    float xv = (q == 0) ? x0 : (q == 1) ? x1 : (q == 2) ? x2 : x3;
                    a[q] = perturb_pack(xv, rb, sigma, (uint32_t)(127 - (lane + 32 * q)));
                }
                topk8_single_accum(a[0], a[1], a[2], a[3], lane, sCnt);
            }
            __syncthreads();
            for (int tt = tid; tt < KK * BB; tt += 256) {
                int v = sCnt[tt];
                if (v) atomicAdd(&cnt[rowb * (KK * BB) + tt], v);
            }
        }

        // chunk done: bump row ticket; last sampled chunk reduces the row
        __threadfence();
        __syncthreads();
        if (tid == 0)
            s_last = ((int)atomicAdd(&g_rowdone[rowb], 1u) == g_rowexp[rowb] - 1);
        __syncthreads();

        if (s_last) {
            float acc = 0.0f;
#pragma unroll
            for (int tt = 0; tt < 4; ++tt) {
                int idx = tt * 256 + tid;
                int c1 = __ldcg(&g_cnt1[rowb * (KK * BB) + idx]);
                int c2 = __ldcg(&g_cnt2[rowb * (KK * BB) + idx]);
                acc = fmaf((float)(c1 * c2), g_tgt[rowb * BB + (idx & 127)], acc);
            }
#pragma unroll
            for (int off = 16; off > 0; off >>= 1)
                acc += __shfl_xor_sync(0xffffffffu, acc, off);
            if (lane == 0) sw[warp] = acc;
            __syncthreads();
            if (tid == 0) {
                float partial = ((sw[0] + sw[1]) + (sw[2] + sw[3]))
                              + ((sw[4] + sw[5]) + (sw[6] + sw[7]));
                long long fx = llrintf(partial * 1048576.0f);
                atomicAdd(&g_sum, (unsigned long long)fx);
                __threadfence();
                if (atomicAdd(&g_done, 1u) == (unsigned)(BB - 1)) {
                    unsigned long long s = atomicAdd(&g_sum, 0ull);
                    out[0] = (float)(-((double)(long long)s / 1048576.0)
                                     / (1000.0 * 1000.0 * (double)(KK * BB)));
                }
            }
        }
    }

    // ================== EXIT + SELF-RESET (replay-safe) ====================
    __threadfence();
    __syncthreads();
    if (tid == 0) {
        if (atomicAdd(&g_exit, 1u) == (unsigned)(NBLK - 1)) {
            // runs strictly after every block's work (incl. the out write)
            for (int r = 0; r < BB; ++r) g_rowdone[r] = 0u;
            g_ticket = 0u; g_done = 0u; g_sum = 0ull; g_nwork = 0; g_exit = 0u;
            __threadfence();
        }
    }
}

// ---------------------------------------------------------------------------
// Launch: 2 kernels
// ---------------------------------------------------------------------------
extern "C" void kernel_launch(void* const* d_in, const int* in_sizes, int n_in,
                              void* d_out, int out_size)
{
    (void)in_sizes; (void)n_in; (void)out_size;
    const float* cad   = (const float*)d_in[0];
    const float* scan  = (const float*)d_in[1];
    const float* sim   = (const float*)d_in[2];
    const int*   sidx  = (const int*)d_in[3];
    const int*   shidx = (const int*)d_in[4];
    float*       out   = (float*)d_out;

    // nk1, nk2 = jax.random.split(jax.random.key(42)); key(42) = (0, 42)
    uint32_t o00, o10, o01, o11;
    threefry2x32(0u, 42u, 0u, 2u, o00, o10);
    threefry2x32(0u, 42u, 1u, 3u, o01, o11);
    uint32_t nk1_0 = o00, nk1_1 = o01;
    uint32_t nk2_0 = o10, nk2_1 = o11;

    const float sig1 = 0.05f;
    const float sig2 = (float)(0.05 / 200.0);
    const float margin1 = 13.0f * sig1;      // > 2*nmax*sigma, nmax<=6
    const float margin2 = 13.0f * sig2;

    prep_kernel<<<BB, 256>>>(cad, scan, sim, sidx, shidx, margin1, margin2, out);
    cand_topk_kernel<<<NBLK, 256>>>(nk1_0, nk1_1, nk2_0, nk2_1, sig1, sig2, out);
}

// round 14
// speedup vs baseline: 1.2314x; 1.2314x over previous
#include <cuda_runtime.h>
#include <cstdint>

// ---------------------------------------------------------------------------
// Problem constants
// ---------------------------------------------------------------------------
#define BB     128          // batch
#define DD     256          // embedding dim
#define NSAMP  1000         // MC samples
#define KK     8            // top-k
#define NSHAPES 8000
#define HALF_ELEMS 8192000u // (128*1000*128)/2 -> element pairing offset
#define MAXC   32           // candidate cap per row (overflow -> inline fallback)
#define CH     20           // chunks per sampling unit (small tickets)
#define SCH    50           // samples per chunk (CH*SCH == NSAMP)
#define NBLK   740          // persistent grid (148 SM x 5 blocks, 1 wave)

// ---------------------------------------------------------------------------
// Device scratch (no allocations; zero-initialized at load, self-reset at the
// end of every cand run for graph replays)
// ---------------------------------------------------------------------------
__device__ float  g_pred[BB * BB];
__device__ float  g_tgt [BB * BB];
__device__ int    g_cnt1[BB * KK * BB];
__device__ int    g_cnt2[BB * KK * BB];
__device__ float  g_cval[2 * BB * MAXC];
__device__ int    g_cidx[2 * BB * MAXC];
__device__ int    g_cm  [2 * BB];
__device__ int    g_wl  [2 * BB];         // worklist: units (pass*128+row), m>8
__device__ int    g_nwork;
__device__ int    g_rowexp[BB];           // expected sampled chunks per row
__device__ unsigned int g_ticket;
__device__ unsigned int g_rowdone[BB];
__device__ unsigned long long g_sum;      // 2^20 fixed-point loss accumulator
__device__ unsigned int g_done;           // rows reduced
__device__ unsigned int g_exit;           // cand blocks exited (reset protocol)

// ---------------------------------------------------------------------------
// threefry2x32 — exactly JAX's schedule
// ---------------------------------------------------------------------------
__host__ __device__ __forceinline__ void threefry2x32(
    uint32_t k0, uint32_t k1, uint32_t x0, uint32_t x1,
    uint32_t& o0, uint32_t& o1)
{
    uint32_t ks2 = k0 ^ k1 ^ 0x1BD11BDAu;
#define TF_ROUND(r) { x0 += x1; x1 = (x1 << (r)) | (x1 >> (32 - (r))); x1 ^= x0; }
    x0 += k0; x1 += k1;
    TF_ROUND(13) TF_ROUND(15) TF_ROUND(26) TF_ROUND(6)
    x0 += k1;  x1 += ks2 + 1u;
    TF_ROUND(17) TF_ROUND(29) TF_ROUND(16) TF_ROUND(24)
    x0 += ks2; x1 += k0 + 2u;
    TF_ROUND(13) TF_ROUND(15) TF_ROUND(26) TF_ROUND(6)
    x0 += k0;  x1 += k1 + 3u;
    TF_ROUND(17) TF_ROUND(29) TF_ROUND(16) TF_ROUND(24)
    x0 += k1;  x1 += ks2 + 4u;
    TF_ROUND(13) TF_ROUND(15) TF_ROUND(26) TF_ROUND(6)
    x0 += ks2; x1 += k0 + 5u;
#undef TF_ROUND
    o0 = x0; o1 = x1;
}

// ---------------------------------------------------------------------------
// bits -> N(0,1): JAX uniform bit-trick + XLA ErfInv32 polynomial (fast log).
// |result| <= ~5.43 always.
// ---------------------------------------------------------------------------
__device__ __forceinline__ float jx_normal(uint32_t bits)
{
    float f = __uint_as_float((bits >> 9) | 0x3f800000u) - 1.0f;   // [0,1)
    const float lo = -0.99999994f;                                  // nextafter(-1,0)
    float u = __fadd_rn(__fmul_rn(f, 2.0f), lo);
    u = fmaxf(u, lo);

    float w = -__logf(fmaf(-u, u, 1.0f));     // ~= -log1p(-u*u)
    float p;
    if (w < 5.0f) {
        w -= 2.5f;
        p = 2.81022636e-08f;
        p = fmaf(p, w,  3.43273939e-07f);
        p = fmaf(p, w, -3.5233877e-06f);
        p = fmaf(p, w, -4.39150654e-06f);
        p = fmaf(p, w,  0.00021858087f);
        p = fmaf(p, w, -0.00125372503f);
        p = fmaf(p, w, -0.00417768164f);
        p = fmaf(p, w,  0.246640727f);
        p = fmaf(p, w,  1.50140941f);
    } else {
        w = sqrtf(w) - 3.0f;
        p = -0.000200214257f;
        p = fmaf(p, w,  0.000100950558f);
        p = fmaf(p, w,  0.00134934322f);
        p = fmaf(p, w, -0.00367342844f);
        p = fmaf(p, w,  0.00573950773f);
        p = fmaf(p, w, -0.0076224613f);
        p = fmaf(p, w,  0.00943887047f);
        p = fmaf(p, w,  1.00167406f);
        p = fmaf(p, w,  2.83297682f);
    }
    return __fmul_rn(1.41421354f, __fmul_rn(p, u));   // sqrt(2)*erfinv(u)
}

// order-isomorphic float map + invidx packing (25-bit value, 7-bit 127-idx)
__device__ __forceinline__ uint32_t pack_key(float v, uint32_t invidx)
{
    uint32_t b = __float_as_uint(v);
    uint32_t k = b ^ ((uint32_t)((int32_t)b >> 31) | 0x80000000u);
    return (k & 0xFFFFFF80u) | invidx;
}

__device__ __forceinline__ uint32_t perturb_pack(float x, uint32_t bits, float sigma,
                                                 uint32_t invidx)
{
    float v = __fadd_rn(x, __fmul_rn(sigma, jx_normal(bits)));
    return pack_key(v, invidx);
}

// decode truncated packed key -> float <= original value
__device__ __forceinline__ float decode_key_low(uint32_t k)
{
    uint32_t kv = k & 0xFFFFFF80u;
    uint32_t b  = (kv & 0x80000000u) ? (kv & 0x7FFFFFFFu) : ~kv;
    return __uint_as_float(b);
}

// ---------------------------------------------------------------------------
// Full-128 helpers
// ---------------------------------------------------------------------------
#define SWAPD(a,b) { uint32_t t_ = (a) < (b) ? (b) : (a); (b) = (a) < (b) ? (a) : (b); (a) = t_; }

__device__ __forceinline__ uint32_t eighth_key(uint32_t a0, uint32_t a1,
                                               uint32_t a2, uint32_t a3)
{
    SWAPD(a0,a1) SWAPD(a2,a3) SWAPD(a0,a2) SWAPD(a1,a3) SWAPD(a1,a2)
    uint32_t mx = 0;
    int pos = 0;
#pragma unroll
    for (int r = 0; r < 8; ++r) {
        mx = __reduce_max_sync(0xffffffffu, a0);
        if (a0 == mx) {
            ++pos;
            a0 = (pos == 1) ? a1 : (pos == 2) ? a2 : (pos == 3) ? a3 : 0u;
        }
    }
    return mx;
}

__device__ __forceinline__ void topk8_single_accum(
    uint32_t a0, uint32_t a1, uint32_t a2, uint32_t a3,
    int lane, int* __restrict__ scnt)
{
    SWAPD(a0,a1) SWAPD(a2,a3) SWAPD(a0,a2) SWAPD(a1,a3) SWAPD(a1,a2)
    uint32_t wonq = 0;
#pragma unroll
    for (int r = 0; r < 8; ++r) {
        uint32_t mx = __reduce_max_sync(0xffffffffu, a0);
        if (a0 == mx) {
            wonq |= 1u << (3u - ((a0 & 127u) >> 5));
            a0 = a1; a1 = a2; a2 = a3; a3 = 0u;
        }
    }
    uint32_t W0 = __ballot_sync(0xffffffffu,  wonq & 1u);
    uint32_t W1 = __ballot_sync(0xffffffffu, (wonq >> 1) & 1u);
    uint32_t W2 = __ballot_sync(0xffffffffu, (wonq >> 2) & 1u);
    uint32_t W3 = __ballot_sync(0xffffffffu, (wonq >> 3) & 1u);

    int r = lane & 7;
    int c0 = __popc(W0);
    int c01 = c0 + __popc(W1);
    int c012 = c01 + __popc(W2);
    uint32_t word = W0; int base = 0, n = r;
    if (r >= c0)   { word = W1; base = 32; n = r - c0; }
    if (r >= c01)  { word = W2; base = 64; n = r - c01; }
    if (r >= c012) { word = W3; base = 96; n = r - c012; }

    unsigned pos = 0, c;
    c = __popc(word & 0xFFFFu); if ((unsigned)n >= c) { n -= c; pos += 16; word >>= 16; }
    c = __popc(word & 0xFFu);   if ((unsigned)n >= c) { n -= c; pos += 8;  word >>= 8; }
    c = __popc(word & 0xFu);    if ((unsigned)n >= c) { n -= c; pos += 4;  word >>= 4; }
    c = __popc(word & 0x3u);    if ((unsigned)n >= c) { n -= c; pos += 2;  word >>= 2; }
    c = word & 1u;              if ((unsigned)n >= c) { pos += 1; }

    if (lane < 8)
        atomicAdd(&scnt[r * BB + base + (int)pos], 1);
}

// ---------------------------------------------------------------------------
// Kernel 1: pred_sim GEMM (split-K) + tgt gather + zeroing + candidates
// + worklist + m==8 deterministic counts + fully-deterministic-row reduction.
// grid(128) block(256). Relies on run-state zeroed by previous cand run.
// ---------------------------------------------------------------------------
__global__ void __launch_bounds__(256) prep_kernel(
    const float* __restrict__ cad, const float* __restrict__ scan,
    const float* __restrict__ sim, const int* __restrict__ scannet_idx,
    const int* __restrict__ shapenet_idx,
    float margin1, float margin2, float* __restrict__ out)
{
    __shared__ float row[DD];
    __shared__ float s_pred[BB], s_tg[BB];
    __shared__ float s_part[256];
    __shared__ int   s_m[2];
    __shared__ int   s_rd[2][8];
    int i = blockIdx.x, tid = threadIdx.x;
    int j = tid & 127, h = tid >> 7;

    if (tid < 128) {
        row[tid]       = scan[i * DD + tid];
        row[tid + 128] = scan[i * DD + 128 + tid];
    }
    {   // zero row i of both counter arrays
        int t = i * 256 + tid;
        int4 z = make_int4(0, 0, 0, 0);
        reinterpret_cast<int4*>(g_cnt1)[t] = z;
        reinterpret_cast<int4*>(g_cnt2)[t] = z;
    }
    __syncthreads();

    const float4* c4 = reinterpret_cast<const float4*>(cad + (size_t)j * DD) + h * 32;
    float a0 = 0.f, a1 = 0.f, a2 = 0.f, a3 = 0.f;
#pragma unroll
    for (int t = 0; t < 32; ++t) {
        float4 v = c4[t];
        int base = h * 128 + t * 4;
        a0 = fmaf(row[base + 0], v.x, a0);
        a1 = fmaf(row[base + 1], v.y, a1);
        a2 = fmaf(row[base + 2], v.z, a2);
        a3 = fmaf(row[base + 3], v.w, a3);
    }
    s_part[tid] = (a0 + a1) + (a2 + a3);
    __syncthreads();

    if (tid < 128) {
        float acc = s_part[tid] + s_part[tid + 128];
        float tv  = sim[(size_t)scannet_idx[i] * NSHAPES + shapenet_idx[tid]];
        g_pred[i * BB + tid] = acc;  s_pred[tid] = acc;
        g_tgt [i * BB + tid] = tv;   s_tg[tid]   = tv;
    }
    __syncthreads();

    int w = tid >> 5, lane = tid & 31;
    if (w < 2) {
        const float* v = w ? s_tg : s_pred;
        float margin = w ? margin2 : margin1;
        int* __restrict__ cnt = w ? g_cnt2 : g_cnt1;
        float v0 = v[lane], v1 = v[lane + 32], v2 = v[lane + 64], v3 = v[lane + 96];

        uint32_t k8 = eighth_key(pack_key(v0, 127u - lane),
                                 pack_key(v1, 95u  - lane),
                                 pack_key(v2, 63u  - lane),
                                 pack_key(v3, 31u  - lane));
        float thresh = decode_key_low(k8) - margin;

        int cbase = (w * BB + i) * MAXC;
        int mycand[4]; int mycnt = 0;
        int cnt_total = 0;
#pragma unroll
        for (int q = 0; q < 4; ++q) {
            float vq = (q == 0) ? v0 : (q == 1) ? v1 : (q == 2) ? v2 : v3;
            bool c = (vq >= thresh);
            uint32_t mask = __ballot_sync(0xffffffffu, c);
            if (c) {
                int pos = cnt_total + __popc(mask & ((1u << lane) - 1u));
                if (pos < MAXC) {
                    g_cval[cbase + pos] = vq;
                    g_cidx[cbase + pos] = q * 32 + lane;
                }
                if (pos < 8) s_rd[w][pos] = q * 32 + lane;
                if (mycnt < 4) mycand[mycnt] = (pos << 16) | (q * 32 + lane);
                ++mycnt;
            }
            cnt_total += __popc(mask);
        }
        if (lane == 0) {
            g_cm[w * BB + i] = cnt_total;
            s_m[w] = cnt_total;
            if (cnt_total > 8) {
                int p = atomicAdd(&g_nwork, 1);
                g_wl[p] = w * BB + i;
            }
        }

        if (cnt_total == 8) {   // deterministic counts
#pragma unroll
            for (int t = 0; t < 4; ++t) {
                if (t < mycnt) {
                    int pos = mycand[t] >> 16;
                    int d   = mycand[t] & 0xFFFF;
                    cnt[i * (KK * BB) + pos * BB + d] = NSAMP;
                }
            }
        }
    }
    __syncthreads();

    if (tid == 0) {
        int expv = ((s_m[0] > 8) ? CH : 0) + ((s_m[1] > 8) ? CH : 0);
        g_rowexp[i] = expv;
        if (expv == 0) {   // fully deterministic row: reduce right here
            float part = 0.0f;
#pragma unroll
            for (int r = 0; r < 8; ++r)
                if (s_rd[0][r] == s_rd[1][r]) part += s_tg[s_rd[0][r]];
            part *= (float)NSAMP * (float)NSAMP;
            long long fx = llrintf(part * 1048576.0f);
            atomicAdd(&g_sum, (unsigned long long)fx);
            __threadfence();
            if (atomicAdd(&g_done, 1u) == (unsigned)(BB - 1)) {
                unsigned long long s = atomicAdd(&g_sum, 0ull);
                out[0] = (float)(-((double)(long long)s / 1048576.0)
                                 / (1000.0 * 1000.0 * (double)(KK * BB)));
            }
        }
    }
}

// ---------------------------------------------------------------------------
// Kernel 2: persistent ticket sampler (2-way ILP) + fused reduction + reset.
// grid(NBLK) block(256). Tickets: t -> (unit = g_wl[t/CH], chunk = t%CH).
// ---------------------------------------------------------------------------
__global__ void __launch_bounds__(256, 5) cand_topk_kernel(
    uint32_t k0a, uint32_t k1a, uint32_t k0b, uint32_t k1b,
    float sig1, float sig2, float* __restrict__ out)
{
    __shared__ int   sCnt[KK * BB];
    __shared__ unsigned int s_t;
    __shared__ int   s_last;
    __shared__ float sw[8];

    int tid = threadIdx.x, lane = tid & 31, warp = tid >> 5;
    unsigned int total = (unsigned int)(g_nwork * CH);

    for (;;) {
        __syncthreads();                        // protect shared reuse
        if (tid == 0) s_t = atomicAdd(&g_ticket, 1u);
        __syncthreads();
        unsigned int t = s_t;
        if (t >= total) break;

        int unit  = g_wl[t / CH];
        int chunk = (int)(t % CH);
        int pass  = unit >> 7;
        int rowb  = unit & 127;

        int*     __restrict__ cnt = pass ? g_cnt2 : g_cnt1;
        uint32_t k0 = pass ? k0b : k0a;
        uint32_t k1 = pass ? k1b : k1a;
        float sigma = pass ? sig2 : sig1;

        int m = g_cm[unit];
        uint32_t rowbase = (uint32_t)rowb * (uint32_t)(NSAMP * BB);
        bool lohalf = rowb < 64;
        int nBegin = chunk * SCH;
        int nEnd   = nBegin + SCH;
        int cbase  = unit * MAXC;

        if (m <= MAXC) {
            if (tid < KK * MAXC) sCnt[tid] = 0;

            int nseg = 32 / m;
            int seg  = lane / m;
            int slot = lane - seg * m;
            bool active = seg < nseg;
            uint32_t segmask = ((m == 32) ? 0xffffffffu : ((1u << m) - 1u)) << (seg * m);

            float    x   = active ? g_cval[cbase + slot] : 0.0f;
            int      d   = active ? g_cidx[cbase + slot] : 0;
            uint32_t inv = 127u - (uint32_t)d;
            __syncthreads();

            int roundsMin = m - 8;
            bool useMin = (roundsMin <= 8);
            uint32_t ebase = rowbase + (uint32_t)d;

            for (int n0 = nBegin + warp * nseg; n0 < nEnd; n0 += 16 * nseg) {
                int nnA = n0 + seg;
                int nnB = n0 + 8 * nseg + seg;
                bool validA = active && (nnA < nEnd);
                bool validB = active && (nnB < nEnd);

                // two independent threefry/erfinv chains (ILP)
                uint32_t eA = ebase + (uint32_t)nnA * (uint32_t)BB;
                uint32_t eB = ebase + (uint32_t)nnB * (uint32_t)BB;
                uint32_t txA0 = lohalf ? eA : eA - HALF_ELEMS;
                uint32_t txA1 = lohalf ? eA + HALF_ELEMS : eA;
                uint32_t txB0 = lohalf ? eB : eB - HALF_ELEMS;
                uint32_t txB1 = lohalf ? eB + HALF_ELEMS : eB;
                uint32_t oA0, oA1, oB0, oB1;
                threefry2x32(k0, k1, txA0, txA1, oA0, oA1);
                threefry2x32(k0, k1, txB0, txB1, oB0, oB1);
                uint32_t keyA = perturb_pack(x, lohalf ? oA0 : oA1, sigma, inv);
                uint32_t keyB = perturb_pack(x, lohalf ? oB0 : oB1, sigma, inv);

                bool wonA = false, wonB = false;
                if (validA) {
                    uint32_t key = keyA;
                    if (useMin) {
                        bool elim = false;
                        for (int r = 0; r < roundsMin; ++r) {
                            uint32_t mn = __reduce_min_sync(segmask, key);
                            bool er = (key == mn);
                            elim |= er;
                            if (er) key = 0xFFFFFFFFu;
                        }
                        wonA = !elim;
                    } else {
                        for (int r = 0; r < 8; ++r) {
                            uint32_t mx = __reduce_max_sync(segmask, key);
                            bool wr = (key == mx);
                            wonA |= wr;
                            if (wr) key = 0u;
                        }
                    }
                }
                if (validB) {
                    uint32_t key = keyB;
                    if (useMin) {
                        bool elim = false;
                        for (int r = 0; r < roundsMin; ++r) {
                            uint32_t mn = __reduce_min_sync(segmask, key);
                            bool er = (key == mn);
                            elim |= er;
                            if (er) key = 0xFFFFFFFFu;
                        }
                        wonB = !elim;
                    } else {
                        for (int r = 0; r < 8; ++r) {
                            uint32_t mx = __reduce_max_sync(segmask, key);
                            bool wr = (key == mx);
                            wonB |= wr;
                            if (wr) key = 0u;
                        }
                    }
                }
                uint32_t balA = __ballot_sync(0xffffffffu, wonA);
                uint32_t balB = __ballot_sync(0xffffffffu, wonB);
                if (wonA) {
                    int rank = __popc(balA & segmask & ((1u << lane) - 1u));
                    atomicAdd(&sCnt[rank * MAXC + slot], 1);
                }
                if (wonB) {
                    int rank = __popc(balB & segmask & ((1u << lane) - 1u));
                    atomicAdd(&sCnt[rank * MAXC + slot], 1);
                }
            }
            __syncthreads();

            for (int tt = tid; tt < KK * m; tt += 256) {
                int rank = tt / m, sl = tt - rank * m;
                int v = sCnt[rank * MAXC + sl];
                if (v) atomicAdd(&cnt[rowb * (KK * BB) + rank * BB + g_cidx[cbase + sl]], v);
            }
        } else {
            // full-128 fallback (m > MAXC; astronomically rare)
            for (int tt = tid; tt < KK * BB; tt += 256) sCnt[tt] = 0;
            __syncthreads();

            const float* __restrict__ src = pass ? g_tgt : g_pred;
            float x0 = src[rowb * BB + lane];
            float x1 = src[rowb * BB + lane + 32];
            float x2 = src[rowb * BB + lane + 64];
            float x3 = src[rowb * BB + lane + 96];
            for (int n = nBegin + warp; n < nEnd; n += 8) {
                uint32_t a[4];
#pragma unroll
                for (int q = 0; q < 4; ++q) {
                    uint32_t e   = rowbase + (uint32_t)n * (uint32_t)BB + (uint32_t)(lane + 32 * q);
                    uint32_t tx0 = lohalf ? e : e - HALF_ELEMS;
                    uint32_t tx1 = lohalf ? e + HALF_ELEMS : e;
                    uint32_t o0, o1;
                    threefry2x32(k0, k1, tx0, tx1, o0, o1);
                    uint32_t rb = lohalf ? o0 : o1;
                    float xv = (q == 0) ? x0 : (q == 1) ? x1 : (q == 2) ? x2 : x3;
                    a[q] = perturb_pack(xv, rb, sigma, (uint32_t)(127 - (lane + 32 * q)));
                }
                topk8_single_accum(a[0], a[1], a[2], a[3], lane, sCnt);
            }
            __syncthreads();
            for (int tt = tid; tt < KK * BB; tt += 256) {
                int v = sCnt[tt];
                if (v) atomicAdd(&cnt[rowb * (KK * BB) + tt], v);
            }
        }

        // chunk done: bump row ticket; last sampled chunk reduces the row
        __threadfence();
        __syncthreads();
        if (tid == 0)
            s_last = ((int)atomicAdd(&g_rowdone[rowb], 1u) == g_rowexp[rowb] - 1);
        __syncthreads();

        if (s_last) {
            float acc = 0.0f;
#pragma unroll
            for (int tt = 0; tt < 4; ++tt) {
                int idx = tt * 256 + tid;
                int c1 = __ldcg(&g_cnt1[rowb * (KK * BB) + idx]);
                int c2 = __ldcg(&g_cnt2[rowb * (KK * BB) + idx]);
                acc = fmaf((float)(c1 * c2), g_tgt[rowb * BB + (idx & 127)], acc);
            }
#pragma unroll
            for (int off = 16; off > 0; off >>= 1)
                acc += __shfl_xor_sync(0xffffffffu, acc, off);
            if (lane == 0) sw[warp] = acc;
            __syncthreads();
            if (tid == 0) {
                float partial = ((sw[0] + sw[1]) + (sw[2] + sw[3]))
                              + ((sw[4] + sw[5]) + (sw[6] + sw[7]));
                long long fx = llrintf(partial * 1048576.0f);
                atomicAdd(&g_sum, (unsigned long long)fx);
                __threadfence();
                if (atomicAdd(&g_done, 1u) == (unsigned)(BB - 1)) {
                    unsigned long long s = atomicAdd(&g_sum, 0ull);
                    out[0] = (float)(-((double)(long long)s / 1048576.0)
                                     / (1000.0 * 1000.0 * (double)(KK * BB)));
                }
            }
        }
    }

    // ================== EXIT + SELF-RESET (replay-safe) ====================
    __threadfence();
    __syncthreads();
    if (tid == 0) {
        if (atomicAdd(&g_exit, 1u) == (unsigned)(NBLK - 1)) {
            // runs strictly after every block's work (incl. the out write)
            for (int r = 0; r < BB; ++r) g_rowdone[r] = 0u;
            g_ticket = 0u; g_done = 0u; g_sum = 0ull; g_nwork = 0; g_exit = 0u;
            __threadfence();
        }
    }
}

// ---------------------------------------------------------------------------
// Launch: 2 kernels
// ---------------------------------------------------------------------------
extern "C" void kernel_launch(void* const* d_in, const int* in_sizes, int n_in,
                              void* d_out, int out_size)
{
    (void)in_sizes; (void)n_in; (void)out_size;
    const float* cad   = (const float*)d_in[0];
    const float* scan  = (const float*)d_in[1];
    const float* sim   = (const float*)d_in[2];
    const int*   sidx  = (const int*)d_in[3];
    const int*   shidx = (const int*)d_in[4];
    float*       out   = (float*)d_out;

    // nk1, nk2 = jax.random.split(jax.random.key(42)); key(42) = (0, 42)
    uint32_t o00, o10, o01, o11;
    threefry2x32(0u, 42u, 0u, 2u, o00, o10);
    threefry2x32(0u, 42u, 1u, 3u, o01, o11);
    uint32_t nk1_0 = o00, nk1_1 = o01;
    uint32_t nk2_0 = o10, nk2_1 = o11;

    const float sig1 = 0.05f;
    const float sig2 = (float)(0.05 / 200.0);
    const float margin1 = 11.0f * sig1;      // > 2*nmax*sigma, nmax<=5.43
    const float margin2 = 11.0f * sig2;

    prep_kernel<<<BB, 256>>>(cad, scan, sim, sidx, shidx, margin1, margin2, out);
    cand_topk_kernel<<<NBLK, 256>>>(nk1_0, nk1_1, nk2_0, nk2_1, sig1, sig2, out);
}

// round 15
// speedup vs baseline: 1.4441x; 1.1728x over previous
#include <cuda_runtime.h>
#include <cstdint>

// ---------------------------------------------------------------------------
// Problem constants
// ---------------------------------------------------------------------------
#define BB     128          // batch
#define DD     256          // embedding dim
#define NSAMP  1000         // MC samples
#define KK     8            // top-k
#define NSHAPES 8000
#define HALF_ELEMS 8192000u // (128*1000*128)/2 -> element pairing offset
#define MAXC   32           // candidate cap per row (overflow -> inline fallback)
#define NCHUNK 5            // sample chunks per (row,pass): 200 samples each

// ---------------------------------------------------------------------------
// Device scratch (no allocations allowed)
// ---------------------------------------------------------------------------
__device__ float  g_pred[BB * BB];
__device__ float  g_tgt [BB * BB];
__device__ int    g_cnt1[BB * KK * BB];   // pred-side indicator counts
__device__ int    g_cnt2[BB * KK * BB];   // tgt-side indicator counts
__device__ float  g_cval[2 * BB * MAXC];  // candidate base values
__device__ int    g_cidx[2 * BB * MAXC];  // candidate global indices (ascending)
__device__ int    g_cm  [2 * BB];         // candidate counts
__device__ unsigned int g_rowdone[BB];    // per-row block completion tickets
__device__ unsigned long long g_sum;      // fixed-point loss accumulator
__device__ unsigned int      g_done;      // row completion ticket

// ---------------------------------------------------------------------------
// threefry2x32 — exactly JAX's schedule
// ---------------------------------------------------------------------------
__host__ __device__ __forceinline__ void threefry2x32(
    uint32_t k0, uint32_t k1, uint32_t x0, uint32_t x1,
    uint32_t& o0, uint32_t& o1)
{
    uint32_t ks2 = k0 ^ k1 ^ 0x1BD11BDAu;
#define TF_ROUND(r) { x0 += x1; x1 = (x1 << (r)) | (x1 >> (32 - (r))); x1 ^= x0; }
    x0 += k0; x1 += k1;
    TF_ROUND(13) TF_ROUND(15) TF_ROUND(26) TF_ROUND(6)
    x0 += k1;  x1 += ks2 + 1u;
    TF_ROUND(17) TF_ROUND(29) TF_ROUND(16) TF_ROUND(24)
    x0 += ks2; x1 += k0 + 2u;
    TF_ROUND(13) TF_ROUND(15) TF_ROUND(26) TF_ROUND(6)
    x0 += k0;  x1 += k1 + 3u;
    TF_ROUND(17) TF_ROUND(29) TF_ROUND(16) TF_ROUND(24)
    x0 += k1;  x1 += ks2 + 4u;
    TF_ROUND(13) TF_ROUND(15) TF_ROUND(26) TF_ROUND(6)
    x0 += ks2; x1 += k0 + 5u;
#undef TF_ROUND
    o0 = x0; o1 = x1;
}

// ---------------------------------------------------------------------------
// bits -> N(0,1): JAX uniform bit-trick + XLA ErfInv32 polynomial (fast log).
// |result| <= ~5.43 always (bounded support of the bit-trick uniform).
// ---------------------------------------------------------------------------
__device__ __forceinline__ float jx_normal(uint32_t bits)
{
    float f = __uint_as_float((bits >> 9) | 0x3f800000u) - 1.0f;   // [0,1)
    const float lo = -0.99999994f;                                  // nextafter(-1,0)
    float u = __fadd_rn(__fmul_rn(f, 2.0f), lo);
    u = fmaxf(u, lo);

    float w = -__logf(fmaf(-u, u, 1.0f));     // ~= -log1p(-u*u)
    float p;
    if (w < 5.0f) {
        w -= 2.5f;
        p = 2.81022636e-08f;
        p = fmaf(p, w,  3.43273939e-07f);
        p = fmaf(p, w, -3.5233877e-06f);
        p = fmaf(p, w, -4.39150654e-06f);
        p = fmaf(p, w,  0.00021858087f);
        p = fmaf(p, w, -0.00125372503f);
        p = fmaf(p, w, -0.00417768164f);
        p = fmaf(p, w,  0.246640727f);
        p = fmaf(p, w,  1.50140941f);
    } else {
        w = sqrtf(w) - 3.0f;
        p = -0.000200214257f;
        p = fmaf(p, w,  0.000100950558f);
        p = fmaf(p, w,  0.00134934322f);
        p = fmaf(p, w, -0.00367342844f);
        p = fmaf(p, w,  0.00573950773f);
        p = fmaf(p, w, -0.0076224613f);
        p = fmaf(p, w,  0.00943887047f);
        p = fmaf(p, w,  1.00167406f);
        p = fmaf(p, w,  2.83297682f);
    }
    return __fmul_rn(1.41421354f, __fmul_rn(p, u));   // sqrt(2)*erfinv(u)
}

// order-isomorphic float map + invidx packing (25-bit value, 7-bit 127-idx)
__device__ __forceinline__ uint32_t pack_key(float v, uint32_t invidx)
{
    uint32_t b = __float_as_uint(v);
    uint32_t k = b ^ ((uint32_t)((int32_t)b >> 31) | 0x80000000u);
    return (k & 0xFFFFFF80u) | invidx;
}

__device__ __forceinline__ uint32_t perturb_pack(float x, uint32_t bits, float sigma,
                                                 uint32_t invidx)
{
    float v = __fadd_rn(x, __fmul_rn(sigma, jx_normal(bits)));
    return pack_key(v, invidx);
}

// decode truncated packed key -> float that is <= the original value
__device__ __forceinline__ float decode_key_low(uint32_t k)
{
    uint32_t kv = k & 0xFFFFFF80u;
    uint32_t b  = (kv & 0x80000000u) ? (kv & 0x7FFFFFFFu) : ~kv;
    return __uint_as_float(b);
}

// ---------------------------------------------------------------------------
// Full-128 helpers (prep threshold + inline fallback)
// ---------------------------------------------------------------------------
#define SWAPD(a,b) { uint32_t t_ = (a) < (b) ? (b) : (a); (b) = (a) < (b) ? (a) : (b); (a) = t_; }

__device__ __forceinline__ uint32_t eighth_key(uint32_t a0, uint32_t a1,
                                               uint32_t a2, uint32_t a3)
{
    SWAPD(a0,a1) SWAPD(a2,a3) SWAPD(a0,a2) SWAPD(a1,a3) SWAPD(a1,a2)
    uint32_t mx = 0;
    int pos = 0;
#pragma unroll
    for (int r = 0; r < 8; ++r) {
        mx = __reduce_max_sync(0xffffffffu, a0);
        if (a0 == mx) {
            ++pos;
            a0 = (pos == 1) ? a1 : (pos == 2) ? a2 : (pos == 3) ? a3 : 0u;
        }
    }
    return mx;
}

__device__ __forceinline__ void topk8_single_accum(
    uint32_t a0, uint32_t a1, uint32_t a2, uint32_t a3,
    int lane, int* __restrict__ scnt)
{
    SWAPD(a0,a1) SWAPD(a2,a3) SWAPD(a0,a2) SWAPD(a1,a3) SWAPD(a1,a2)
    uint32_t wonq = 0;
#pragma unroll
    for (int r = 0; r < 8; ++r) {
        uint32_t mx = __reduce_max_sync(0xffffffffu, a0);
        if (a0 == mx) {
            wonq |= 1u << (3u - ((a0 & 127u) >> 5));
            a0 = a1; a1 = a2; a2 = a3; a3 = 0u;
        }
    }
    uint32_t W0 = __ballot_sync(0xffffffffu,  wonq & 1u);
    uint32_t W1 = __ballot_sync(0xffffffffu, (wonq >> 1) & 1u);
    uint32_t W2 = __ballot_sync(0xffffffffu, (wonq >> 2) & 1u);
    uint32_t W3 = __ballot_sync(0xffffffffu, (wonq >> 3) & 1u);

    int r = lane & 7;
    int c0 = __popc(W0);
    int c01 = c0 + __popc(W1);
    int c012 = c01 + __popc(W2);
    uint32_t word = W0; int base = 0, n = r;
    if (r >= c0)   { word = W1; base = 32; n = r - c0; }
    if (r >= c01)  { word = W2; base = 64; n = r - c01; }
    if (r >= c012) { word = W3; base = 96; n = r - c012; }

    unsigned pos = 0, c;
    c = __popc(word & 0xFFFFu); if ((unsigned)n >= c) { n -= c; pos += 16; word >>= 16; }
    c = __popc(word & 0xFFu);   if ((unsigned)n >= c) { n -= c; pos += 8;  word >>= 8; }
    c = __popc(word & 0xFu);    if ((unsigned)n >= c) { n -= c; pos += 4;  word >>= 4; }
    c = __popc(word & 0x3u);    if ((unsigned)n >= c) { n -= c; pos += 2;  word >>= 2; }
    c = word & 1u;              if ((unsigned)n >= c) { pos += 1; }

    if (lane < 8)
        atomicAdd(&scnt[r * BB + base + (int)pos], 1);
}

// ---------------------------------------------------------------------------
// Kernel 1: pred_sim GEMM (split-K) + tgt gather + zeroing + candidates.
// m == 8 rows get deterministic counts written directly.
// grid(128) block(256). Block i owns row i.
// ---------------------------------------------------------------------------
__global__ void __launch_bounds__(256) prep_kernel(
    const float* __restrict__ cad, const float* __restrict__ scan,
    const float* __restrict__ sim, const int* __restrict__ scannet_idx,
    const int* __restrict__ shapenet_idx,
    float margin1, float margin2)           // 11*sigma per pass
{
    __shared__ float row[DD];
    __shared__ float s_pred[BB], s_tgt[BB];
    __shared__ float s_part[256];
    int i = blockIdx.x, tid = threadIdx.x;
    int j = tid & 127, h = tid >> 7;

    if (tid < 128) {
        row[tid]       = scan[i * DD + tid];
        row[tid + 128] = scan[i * DD + 128 + tid];
    }
    // zero row i of both counter arrays
    {
        int t = i * 256 + tid;
        int4 z = make_int4(0, 0, 0, 0);
        reinterpret_cast<int4*>(g_cnt1)[t] = z;
        reinterpret_cast<int4*>(g_cnt2)[t] = z;
    }
    if (i == 0) {
        if (tid < BB) g_rowdone[tid] = 0u;
        if (tid == 0) { g_sum = 0ull; g_done = 0u; }
    }
    __syncthreads();

    // half dot product: cad[j][h*128 .. h*128+127] . row[h*128 ..]
    const float4* c4 = reinterpret_cast<const float4*>(cad + (size_t)j * DD) + h * 32;
    float a0 = 0.f, a1 = 0.f, a2 = 0.f, a3 = 0.f;
#pragma unroll
    for (int t = 0; t < 32; ++t) {
        float4 v = c4[t];
        int base = h * 128 + t * 4;
        a0 = fmaf(row[base + 0], v.x, a0);
        a1 = fmaf(row[base + 1], v.y, a1);
        a2 = fmaf(row[base + 2], v.z, a2);
        a3 = fmaf(row[base + 3], v.w, a3);
    }
    s_part[tid] = (a0 + a1) + (a2 + a3);
    __syncthreads();

    if (tid < 128) {
        float acc = s_part[tid] + s_part[tid + 128];
        float tv  = sim[(size_t)scannet_idx[i] * NSHAPES + shapenet_idx[tid]];
        g_pred[i * BB + tid] = acc;  s_pred[tid] = acc;
        g_tgt [i * BB + tid] = tv;   s_tgt[tid]  = tv;
    }
    __syncthreads();

    int w = tid >> 5, lane = tid & 31;
    if (w < 2) {
        const float* v = w ? s_tgt : s_pred;
        float margin = w ? margin2 : margin1;
        int* __restrict__ cnt = w ? g_cnt2 : g_cnt1;
        float v0 = v[lane], v1 = v[lane + 32], v2 = v[lane + 64], v3 = v[lane + 96];

        uint32_t k8 = eighth_key(pack_key(v0, 127u - lane),
                                 pack_key(v1, 95u  - lane),
                                 pack_key(v2, 63u  - lane),
                                 pack_key(v3, 31u  - lane));
        float thresh = decode_key_low(k8) - margin;

        int cbase = (w * BB + i) * MAXC;
        int mycand[4]; int mycnt = 0;       // this lane's (pos,idx) records
        int cnt_total = 0;
#pragma unroll
        for (int q = 0; q < 4; ++q) {
            float vq = (q == 0) ? v0 : (q == 1) ? v1 : (q == 2) ? v2 : v3;
            bool c = (vq >= thresh);
            uint32_t mask = __ballot_sync(0xffffffffu, c);
            if (c) {
                int pos = cnt_total + __popc(mask & ((1u << lane) - 1u));
                if (pos < MAXC) {
                    g_cval[cbase + pos] = vq;
                    g_cidx[cbase + pos] = q * 32 + lane;
                }
                if (mycnt < 4)
                    mycand[mycnt] = (pos << 16) | (q * 32 + lane);
                ++mycnt;
            }
            cnt_total += __popc(mask);
        }
        if (lane == 0) g_cm[w * BB + i] = cnt_total;

        // m == 8: counts are deterministic -> cnt[rank*BB + d] = NSAMP
        if (cnt_total == 8) {
#pragma unroll
            for (int t = 0; t < 4; ++t) {
                if (t < mycnt) {
                    int pos = mycand[t] >> 16;
                    int d   = mycand[t] & 0xFFFF;
                    cnt[i * (KK * BB) + pos * BB + d] = NSAMP;
                }
            }
        }
    }
}

// ---------------------------------------------------------------------------
// Kernel 2: candidate-pruned noise + top-8 counting + fused reduction.
// grid(128, NCHUNK, 2) block(256). m==8: skip sampling (counts from prep).
// 8<m<=32: dynamic segmentation + 2-way sample ILP + loser-elimination.
// m>32: full-128 fallback. Row ticket over 2*NCHUNK -> fused reduction.
// ---------------------------------------------------------------------------
__global__ void __launch_bounds__(256, 5) cand_topk_kernel(
    uint32_t k0a, uint32_t k1a, uint32_t k0b, uint32_t k1b,
    float sig1, float sig2, int nPerChunk, float* __restrict__ out)
{
    int pass = blockIdx.z;
    int rowb = blockIdx.x;

    __shared__ int   sCnt[KK * BB];   // fallback uses all; pruned uses [KK*MAXC]
    __shared__ int   s_last;
    __shared__ float sw[8];

    int*     __restrict__ cnt = pass ? g_cnt2 : g_cnt1;
    uint32_t k0 = pass ? k0b : k0a;
    uint32_t k1 = pass ? k1b : k1a;
    float sigma = pass ? sig2 : sig1;

    int tid = threadIdx.x;
    int lane = tid & 31, warp = tid >> 5;

    int m = g_cm[pass * BB + rowb];
    uint32_t rowbase = (uint32_t)rowb * (uint32_t)(NSAMP * BB);
    bool lohalf = rowb < 64;
    int nBegin = blockIdx.y * nPerChunk;
    int nEnd   = nBegin + nPerChunk;
    int cbase  = (pass * BB + rowb) * MAXC;

    if (m > 8 && m <= MAXC) {
        if (tid < KK * MAXC) sCnt[tid] = 0;

        int nseg = 32 / m;
        int seg  = lane / m;
        int slot = lane - seg * m;
        bool active = seg < nseg;
        uint32_t segmask = ((m == 32) ? 0xffffffffu : ((1u << m) - 1u)) << (seg * m);

        float    x   = active ? g_cval[cbase + slot] : 0.0f;
        int      d   = active ? g_cidx[cbase + slot] : 0;
        uint32_t inv = 127u - (uint32_t)d;
        __syncthreads();

        int roundsMin = m - 8;
        bool useMin = (roundsMin <= 8);
        uint32_t ebase = rowbase + (uint32_t)d;

        for (int n0 = nBegin + warp * nseg; n0 < nEnd; n0 += 16 * nseg) {
            int nnA = n0 + seg;
            int nnB = n0 + 8 * nseg + seg;
            bool validA = active && (nnA < nEnd);
            bool validB = active && (nnB < nEnd);

            // two independent threefry/erfinv chains (ILP)
            uint32_t eA = ebase + (uint32_t)nnA * (uint32_t)BB;
            uint32_t eB = ebase + (uint32_t)nnB * (uint32_t)BB;
            uint32_t txA0 = lohalf ? eA : eA - HALF_ELEMS;
            uint32_t txA1 = lohalf ? eA + HALF_ELEMS : eA;
            uint32_t txB0 = lohalf ? eB : eB - HALF_ELEMS;
            uint32_t txB1 = lohalf ? eB + HALF_ELEMS : eB;
            uint32_t oA0, oA1, oB0, oB1;
            threefry2x32(k0, k1, txA0, txA1, oA0, oA1);
            threefry2x32(k0, k1, txB0, txB1, oB0, oB1);
            uint32_t keyA = perturb_pack(x, lohalf ? oA0 : oA1, sigma, inv);
            uint32_t keyB = perturb_pack(x, lohalf ? oB0 : oB1, sigma, inv);

            bool wonA = false, wonB = false;
            if (validA) {
                uint32_t key = keyA;
                if (useMin) {
                    bool elim = false;
                    for (int r = 0; r < roundsMin; ++r) {
                        uint32_t mn = __reduce_min_sync(segmask, key);
                        bool er = (key == mn);
                        elim |= er;
                        if (er) key = 0xFFFFFFFFu;
                    }
                    wonA = !elim;
                } else {
                    for (int r = 0; r < 8; ++r) {
                        uint32_t mx = __reduce_max_sync(segmask, key);
                        bool wr = (key == mx);
                        wonA |= wr;
                        if (wr) key = 0u;
                    }
                }
            }
            if (validB) {
                uint32_t key = keyB;
                if (useMin) {
                    bool elim = false;
                    for (int r = 0; r < roundsMin; ++r) {
                        uint32_t mn = __reduce_min_sync(segmask, key);
                        bool er = (key == mn);
                        elim |= er;
                        if (er) key = 0xFFFFFFFFu;
                    }
                    wonB = !elim;
                } else {
                    for (int r = 0; r < 8; ++r) {
                        uint32_t mx = __reduce_max_sync(segmask, key);
                        bool wr = (key == mx);
                        wonB |= wr;
                        if (wr) key = 0u;
                    }
                }
            }
            uint32_t balA = __ballot_sync(0xffffffffu, wonA);
            uint32_t balB = __ballot_sync(0xffffffffu, wonB);
            if (wonA) {
                int rank = __popc(balA & segmask & ((1u << lane) - 1u));
                atomicAdd(&sCnt[rank * MAXC + slot], 1);
            }
            if (wonB) {
                int rank = __popc(balB & segmask & ((1u << lane) - 1u));
                atomicAdd(&sCnt[rank * MAXC + slot], 1);
            }
        }
        __syncthreads();

        // compact flush: KK*m entries, slot -> global index via g_cidx
        for (int t = tid; t < KK * m; t += 256) {
            int rank = t / m, sl = t - rank * m;
            int v = sCnt[rank * MAXC + sl];
            if (v) atomicAdd(&cnt[rowb * (KK * BB) + rank * BB + g_cidx[cbase + sl]], v);
        }
    } else if (m > MAXC) {
        // inline full-128 fallback (astronomically rare)
        __shared__ float sVal[BB];
        const float* __restrict__ src = pass ? g_tgt : g_pred;
        for (int t = tid; t < KK * BB; t += 256) sCnt[t] = 0;
        if (tid < BB) sVal[tid] = src[rowb * BB + tid];
        __syncthreads();

        float x0 = sVal[lane], x1 = sVal[lane + 32], x2 = sVal[lane + 64], x3 = sVal[lane + 96];
        for (int n = nBegin + warp; n < nEnd; n += 8) {
            uint32_t a[4];
#pragma unroll
            for (int q = 0; q < 4; ++q) {
                uint32_t e   = rowbase + (uint32_t)n * (uint32_t)BB + (uint32_t)(lane + 32 * q);
                uint32_t tx0 = lohalf ? e : e - HALF_ELEMS;
                uint32_t tx1 = lohalf ? e + HALF_ELEMS : e;
                uint32_t o0, o1;
                threefry2x32(k0, k1, tx0, tx1, o0, o1);
                uint32_t rb = lohalf ? o0 : o1;
                float xv = (q == 0) ? x0 : (q == 1) ? x1 : (q == 2) ? x2 : x3;
                a[q] = perturb_pack(xv, rb, sigma, (uint32_t)(127 - (lane + 32 * q)));
            }
            topk8_single_accum(a[0], a[1], a[2], a[3], lane, sCnt);
        }
        __syncthreads();
        for (int t = tid; t < KK * BB; t += 256) {
            int v = sCnt[t];
            if (v) atomicAdd(&cnt[rowb * (KK * BB) + t], v);
        }
    }
    // m == 8: deterministic counts already written by prep — nothing to do.

    // row ticket: last of the 2*NCHUNK blocks for this row does the reduction
    __threadfence();
    __syncthreads();
    if (tid == 0)
        s_last = (atomicAdd(&g_rowdone[rowb], 1u) == (unsigned)(2 * NCHUNK - 1));
    __syncthreads();

    if (s_last) {
        float acc = 0.0f;
#pragma unroll
        for (int t = 0; t < 4; ++t) {
            int idx = t * 256 + tid;
            int c1 = __ldcg(&g_cnt1[rowb * (KK * BB) + idx]);
            int c2 = __ldcg(&g_cnt2[rowb * (KK * BB) + idx]);
            acc = fmaf((float)(c1 * c2), g_tgt[rowb * BB + (idx & 127)], acc);
        }
#pragma unroll
        for (int off = 16; off > 0; off >>= 1)
            acc += __shfl_xor_sync(0xffffffffu, acc, off);
        if (lane == 0) sw[warp] = acc;
        __syncthreads();
        if (tid == 0) {
            float partial = ((sw[0] + sw[1]) + (sw[2] + sw[3]))
                          + ((sw[4] + sw[5]) + (sw[6] + sw[7]));
            long long fx = llrintf(partial * 1048576.0f);
            atomicAdd(&g_sum, (unsigned long long)fx);
            __threadfence();
            if (atomicAdd(&g_done, 1u) == (unsigned)(BB - 1)) {
                unsigned long long s = atomicAdd(&g_sum, 0ull);
                double total = (double)(long long)s / 1048576.0;
                out[0] = (float)(-total / (1000.0 * 1000.0 * (double)(KK * BB)));
            }
        }
    }
}

// ---------------------------------------------------------------------------
// Launch
// ---------------------------------------------------------------------------
extern "C" void kernel_launch(void* const* d_in, const int* in_sizes, int n_in,
                              void* d_out, int out_size)
{
    (void)in_sizes; (void)n_in; (void)out_size;
    const float* cad   = (const float*)d_in[0];
    const float* scan  = (const float*)d_in[1];
    const float* sim   = (const float*)d_in[2];
    const int*   sidx  = (const int*)d_in[3];
    const int*   shidx = (const int*)d_in[4];
    float*       out   = (float*)d_out;

    // nk1, nk2 = jax.random.split(jax.random.key(42)); key(42) = (0, 42)
    uint32_t o00, o10, o01, o11;
    threefry2x32(0u, 42u, 0u, 2u, o00, o10);
    threefry2x32(0u, 42u, 1u, 3u, o01, o11);
    uint32_t nk1_0 = o00, nk1_1 = o01;
    uint32_t nk2_0 = o10, nk2_1 = o11;

    const float sig1 = 0.05f;
    const float sig2 = (float)(0.05 / 200.0);
    const float margin1 = 11.0f * sig1;      // > 2*nmax*sigma, nmax<=5.43
    const float margin2 = 11.0f * sig2;

    prep_kernel<<<BB, 256>>>(cad, scan, sim, sidx, shidx, margin1, margin2);

    dim3 grid(BB, NCHUNK, 2);
    cand_topk_kernel<<<grid, 256>>>(nk1_0, nk1_1, nk2_0, nk2_1,
                                    sig1, sig2, NSAMP / NCHUNK, out);
}